// round 2
// baseline (speedup 1.0000x reference)
#include <cuda_runtime.h>
#include <cstdint>

#define VOCAB 50000
#define EDIM  256
#define HDIM  256
#define BATCH 64
#define TLEN  2048

// proj_table[v][h] = sum_e emb[v][e] * W_ih[h][e]   (51.2 MB device scratch)
__device__ float g_proj[VOCAB * HDIM];

// ---------------------------------------------------------------------------
// Kernel A: proj = emb @ W_ih^T   (NT SGEMM, C[50000,256])
// CTA tile 128x128, K-chunk 32, 256 threads, 8x8 thread tile.
// ---------------------------------------------------------------------------
__global__ __launch_bounds__(256) void proj_kernel(const float* __restrict__ emb,
                                                   const float* __restrict__ Wih) {
    __shared__ float As[32][128];
    __shared__ float Bs[32][128];

    const int n0 = blockIdx.x * 128;   // 0 or 128
    const int m0 = blockIdx.y * 128;   // vocab tile
    const int tid = threadIdx.x;
    const int tx = tid & 15;           // n-dir
    const int ty = tid >> 4;           // m-dir

    float acc[8][8];
#pragma unroll
    for (int a = 0; a < 8; a++)
#pragma unroll
        for (int bb = 0; bb < 8; bb++) acc[a][bb] = 0.0f;

    for (int kc = 0; kc < EDIM; kc += 32) {
#pragma unroll
        for (int q = 0; q < 4; q++) {
            int fid = tid + 256 * q;       // 0..1023 float4 id
            int row = fid >> 3;            // 0..127
            int col = fid & 7;             // float4 within 32-k chunk
            float4 av = make_float4(0.f, 0.f, 0.f, 0.f);
            int m = m0 + row;
            if (m < VOCAB)
                av = __ldg((const float4*)(emb + (size_t)m * EDIM + kc + col * 4));
            As[col * 4 + 0][row] = av.x;
            As[col * 4 + 1][row] = av.y;
            As[col * 4 + 2][row] = av.z;
            As[col * 4 + 3][row] = av.w;
            float4 bv = __ldg((const float4*)(Wih + (size_t)(n0 + row) * EDIM + kc + col * 4));
            Bs[col * 4 + 0][row] = bv.x;
            Bs[col * 4 + 1][row] = bv.y;
            Bs[col * 4 + 2][row] = bv.z;
            Bs[col * 4 + 3][row] = bv.w;
        }
        __syncthreads();

#pragma unroll
        for (int k = 0; k < 32; k++) {
            float a[8], b[8];
            *(float4*)&a[0] = *(const float4*)&As[k][ty * 8];
            *(float4*)&a[4] = *(const float4*)&As[k][ty * 8 + 4];
            *(float4*)&b[0] = *(const float4*)&Bs[k][tx * 8];
            *(float4*)&b[4] = *(const float4*)&Bs[k][tx * 8 + 4];
#pragma unroll
            for (int ii = 0; ii < 8; ii++)
#pragma unroll
                for (int jj = 0; jj < 8; jj++) acc[ii][jj] += a[ii] * b[jj];
        }
        __syncthreads();
    }

#pragma unroll
    for (int ii = 0; ii < 8; ii++) {
        int m = m0 + ty * 8 + ii;
        if (m < VOCAB) {
            float4 v0 = make_float4(acc[ii][0], acc[ii][1], acc[ii][2], acc[ii][3]);
            float4 v1 = make_float4(acc[ii][4], acc[ii][5], acc[ii][6], acc[ii][7]);
            *(float4*)(g_proj + (size_t)m * HDIM + n0 + tx * 8)     = v0;
            *(float4*)(g_proj + (size_t)m * HDIM + n0 + tx * 8 + 4) = v1;
        }
    }
}

// ---------------------------------------------------------------------------
// Kernel B: RNN scan. 64 clusters (one per batch) x 2 CTAs (output halves).
// Each CTA: 1024 threads, W_hh half-matrix (128 out x 256 K) in registers
// (16 x u64 f32x2 pairs per thread), h exchanged via DSMEM + cluster barrier.
// thread: i = tid&127 (local output), s = tid>>7 (K-slice of 32).
// ---------------------------------------------------------------------------
__device__ __forceinline__ void fma2(unsigned long long& acc,
                                     unsigned long long a,
                                     unsigned long long b) {
    asm("fma.rn.f32x2 %0, %1, %2, %0;" : "+l"(acc) : "l"(a), "l"(b));
}

__global__ void __cluster_dims__(2, 1, 1) __launch_bounds__(1024, 1)
scan_kernel(const int* __restrict__ reviews, const int* __restrict__ lengths,
            const float* __restrict__ Whh, const float* __restrict__ Wcls,
            const float* __restrict__ bcls, float* __restrict__ out) {
    __shared__ __align__(16) float hbuf[2][HDIM];   // full h, double-buffered
    __shared__ float ps[8][128];                    // partial sums
    __shared__ int toks[TLEN];

    const int tid  = threadIdx.x;
    const int b    = blockIdx.x >> 1;
    const int rank = blockIdx.x & 1;
    const int peer = rank ^ 1;
    const int i    = tid & 127;    // local output index
    const int s    = tid >> 7;     // K-slice 0..7 (global K = s*32..s*32+31)
    const int len  = lengths[b];

    for (int idx = tid; idx < TLEN; idx += 1024)
        toks[idx] = reviews[b * TLEN + idx];
    if (tid < HDIM) hbuf[0][tid] = 0.0f;

    // W_hh[rank*128 + i][s*32 .. s*32+31] as 16 packed f32x2 pairs
    unsigned long long w[16];
    {
        const unsigned long long* wp =
            (const unsigned long long*)(Whh + (size_t)(rank * 128 + i) * HDIM + s * 32);
#pragma unroll
        for (int q = 0; q < 16; q++) w[q] = wp[q];
    }
    __syncthreads();

    float xp_cur = 0.0f;
    if (tid < 128) {
        int tok0 = toks[0];
        xp_cur = __ldg(g_proj + (size_t)tok0 * HDIM + rank * 128 + i);
    }

    // prologue arrive (pairs with t=0 wait)
    asm volatile("barrier.cluster.arrive.aligned;" ::: "memory");

    const bool own = ((s >> 2) == rank);   // this slice reads locally-produced h half

    for (int t = 0; t < len; ++t) {
        const int p = t & 1, pn = p ^ 1;

        // prefetch next step's xp (hidden under FMA + barrier)
        float xp_next = 0.0f;
        if (tid < 128) {
            int tn = (t + 1 < len) ? (t + 1) : t;
            int tokn = toks[tn];
            xp_next = __ldg(g_proj + (size_t)tokn * HDIM + rank * 128 + i);
        }

        unsigned long long acc = 0ull;
        const ulonglong2* hp = (const ulonglong2*)&hbuf[p][s * 32];
        if (own) {
#pragma unroll
            for (int q = 0; q < 8; q++) {
                ulonglong2 hh = hp[q];
                fma2(acc, w[2 * q],     hh.x);
                fma2(acc, w[2 * q + 1], hh.y);
            }
        }
        // wait: peer's h-half (DSMEM writes from step t-1) now visible
        asm volatile("barrier.cluster.wait.aligned;" ::: "memory");
        if (!own) {
#pragma unroll
            for (int q = 0; q < 8; q++) {
                ulonglong2 hh = hp[q];
                fma2(acc, w[2 * q],     hh.x);
                fma2(acc, w[2 * q + 1], hh.y);
            }
        }
        float2 af = *(float2*)&acc;
        ps[s][i] = af.x + af.y;
        __syncthreads();

        if (tid < 128) {
            float sum = xp_cur;
#pragma unroll
            for (int q = 0; q < 8; q++) sum += ps[q][i];
            float v = tanhf(sum);
            int off = rank * 128 + i;
            hbuf[pn][off] = v;                          // local copy
            unsigned sa = (unsigned)__cvta_generic_to_shared(&hbuf[pn][off]);
            asm volatile(
                "{ .reg .b32 ra; mapa.shared::cluster.u32 ra, %0, %1;"
                "  st.shared::cluster.f32 [ra], %2; }"
                :: "r"(sa), "r"(peer), "f"(v));
            xp_cur = xp_next;
        }
        __syncthreads();                                // local h visible CTA-wide
        asm volatile("barrier.cluster.arrive.aligned;" ::: "memory"); // release remote sts
    }
    asm volatile("barrier.cluster.wait.aligned;" ::: "memory");  // final exchange visible

    // classifier: rank 0 has the full final h in hbuf[len&1]
    if (rank == 0 && tid < 64) {
        int c = tid >> 5, lane = tid & 31;
        const float* hf = hbuf[len & 1];
        float sum = 0.0f;
#pragma unroll
        for (int m = 0; m < 8; m++)
            sum += Wcls[c * HDIM + lane + 32 * m] * hf[lane + 32 * m];
#pragma unroll
        for (int o = 16; o > 0; o >>= 1) sum += __shfl_down_sync(0xffffffffu, sum, o);
        if (lane == 0) out[b * 2 + c] = sum + bcls[c];
    }
}

// ---------------------------------------------------------------------------
extern "C" void kernel_launch(void* const* d_in, const int* in_sizes, int n_in,
                              void* d_out, int out_size) {
    const int*   reviews = (const int*)d_in[0];
    const int*   lengths = (const int*)d_in[1];
    const float* emb     = (const float*)d_in[2];
    const float* Wih     = (const float*)d_in[3];
    const float* Whh     = (const float*)d_in[4];
    const float* Wcls    = (const float*)d_in[5];
    const float* bcls    = (const float*)d_in[6];
    float*       out     = (float*)d_out;

    dim3 gA(2, (VOCAB + 127) / 128);
    proj_kernel<<<gA, 256>>>(emb, Wih);

    scan_kernel<<<BATCH * 2, 1024>>>(reviews, lengths, Whh, Wcls, bcls, out);
}